// round 1
// baseline (speedup 1.0000x reference)
#include <cuda_runtime.h>
#include <cuda_bf16.h>
#include <cstdint>

#define NUM_HEADS 12
#define NUM_BN 4
#define HIDDEN 768
#define HEAD_DIM 64
#define BATCH 8
#define SEQ 8192
#define NROW 48            // NUM_HEADS * NUM_BN per batch
#define SCALE 0.125f       // 64^-0.5
#define KCH_CTX 8          // k-split chunks for ctx pass
#define TOK_PER_KC (SEQ / KCH_CTX)   // 1024

// ---------------- scratch (static device memory; no allocs allowed) -------
__device__ float g_q[BATCH * NUM_BN * HIDDEN];                 // 24576
__device__ float g_qk[BATCH * NROW * HIDDEN];                  // 294912
__device__ float g_logits[(size_t)BATCH * NROW * SEQ];         // 3145728 (12.6MB)
__device__ float g_rowmax[BATCH * NROW];
__device__ float g_rowinv[BATCH * NROW];
__device__ float g_ctxp[(size_t)KCH_CTX * BATCH * NROW * HIDDEN]; // 9.4MB
__device__ float g_o[BATCH * NUM_BN * HIDDEN];                 // 24576

// ---------------- helpers -------------------------------------------------
__device__ __forceinline__ float to_tf32(float v) {
    uint32_t u;
    asm("cvt.rna.tf32.f32 %0, %1;" : "=r"(u) : "f"(v));
    return __uint_as_float(u);
}

__device__ __forceinline__ void mma_tf32(float* d, const uint32_t* a, const uint32_t* b) {
    asm volatile(
        "mma.sync.aligned.m16n8k8.row.col.f32.tf32.tf32.f32 "
        "{%0,%1,%2,%3}, {%4,%5,%6,%7}, {%8,%9}, {%0,%1,%2,%3};"
        : "+f"(d[0]), "+f"(d[1]), "+f"(d[2]), "+f"(d[3])
        : "r"(a[0]), "r"(a[1]), "r"(a[2]), "r"(a[3]), "r"(b[0]), "r"(b[1]));
}

// ---------------- K1: q = x[:, :4] @ w_q^T --------------------------------
// grid (6 otile, 8 b), 256 thr. Each block: 128 outputs x 4 tokens.
__global__ void __launch_bounds__(256) k_qproj(const float* __restrict__ x,
                                               const float* __restrict__ wq) {
    __shared__ float sX[4][HIDDEN];
    __shared__ float sW[128][65];
    int b = blockIdx.y, o0 = blockIdx.x * 128;
    int tid = threadIdx.x;
    for (int i = tid; i < 4 * HIDDEN; i += 256) {
        int r = i / HIDDEN, c = i % HIDDEN;
        sX[r][c] = x[((size_t)b * SEQ + r) * HIDDEN + c];
    }
    int ol = tid & 127, xp = tid >> 7;   // xp: 0 -> tokens 0,1 ; 1 -> tokens 2,3
    float acc0 = 0.f, acc1 = 0.f;
    for (int kc = 0; kc < 12; kc++) {
        int k0 = kc * 64;
        __syncthreads();
        for (int i = tid; i < 128 * 64; i += 256) {
            int r = i >> 6, c = i & 63;
            sW[r][c] = wq[(size_t)(o0 + r) * HIDDEN + k0 + c];
        }
        __syncthreads();
#pragma unroll 8
        for (int kk = 0; kk < 64; kk++) {
            float w = sW[ol][kk];
            acc0 += sX[xp * 2][k0 + kk] * w;
            acc1 += sX[xp * 2 + 1][k0 + kk] * w;
        }
    }
    g_q[(size_t)(b * 4 + xp * 2) * HIDDEN + o0 + ol] = acc0;
    g_q[(size_t)(b * 4 + xp * 2 + 1) * HIDDEN + o0 + ol] = acc1;
}

// ---------------- K2: qk[b, h*4+x, :] = SCALE * q_h @ Wk_h ----------------
// grid (12 h, 8 b), 256 thr
__global__ void __launch_bounds__(256) k_qk(const float* __restrict__ wkv) {
    int h = blockIdx.x, b = blockIdx.y;
    __shared__ float sQ[4][64];
    __shared__ float sW[32][257];
    int tid = threadIdx.x;
    {
        int xx = tid >> 6, d = tid & 63;
        sQ[xx][d] = g_q[(size_t)(b * 4 + xx) * HIDDEN + h * 64 + d];
    }
    for (int n0 = 0; n0 < HIDDEN; n0 += 256) {
        float a0 = 0.f, a1 = 0.f, a2 = 0.f, a3 = 0.f;
        for (int kc = 0; kc < 2; kc++) {
            __syncthreads();
            for (int i = tid; i < 32 * 256; i += 256) {
                int r = i >> 8, c = i & 255;
                sW[r][c] = wkv[(size_t)(h * 64 + kc * 32 + r) * HIDDEN + n0 + c];
            }
            __syncthreads();
#pragma unroll
            for (int d = 0; d < 32; d++) {
                float w = sW[d][tid];
                int kd = kc * 32 + d;
                a0 += sQ[0][kd] * w;
                a1 += sQ[1][kd] * w;
                a2 += sQ[2][kd] * w;
                a3 += sQ[3][kd] * w;
            }
        }
        size_t rb = (size_t)(b * NROW + h * 4) * HIDDEN + n0 + tid;
        g_qk[rb] = a0 * SCALE;
        g_qk[rb + HIDDEN] = a1 * SCALE;
        g_qk[rb + 2 * HIDDEN] = a2 * SCALE;
        g_qk[rb + 3 * HIDDEN] = a3 * SCALE;
    }
}

// ---------------- K3: logits[b, 48, S] = qk[b] @ x[b]^T (tf32 mma) --------
// grid (64 token-tiles, 8 b), 128 thr (4 warps). Tile: M=48, N=128, K=768.
__global__ void __launch_bounds__(128) k_logits(const float* __restrict__ x) {
    int b = blockIdx.y;
    int tok0 = blockIdx.x * 128;
    int tid = threadIdx.x;
    int warp = tid >> 5, lane = tid & 31;
    int g = lane >> 2, t = lane & 3;
    __shared__ float sQ[48][36];
    __shared__ float sX[128][36];
    float acc[3][4][4];
#pragma unroll
    for (int m = 0; m < 3; m++)
#pragma unroll
        for (int n = 0; n < 4; n++)
#pragma unroll
            for (int i = 0; i < 4; i++) acc[m][n][i] = 0.f;

    const float* xb = x + (size_t)b * SEQ * HIDDEN;
    for (int kc = 0; kc < 24; kc++) {
        int k0 = kc * 32;
#pragma unroll
        for (int i = 0; i < 3; i++) {
            int idx = tid + i * 128;             // 0..383
            int r = idx >> 3, c4 = idx & 7;
            float4 v = *(const float4*)(g_qk + ((size_t)b * NROW + r) * HIDDEN + k0 + c4 * 4);
            sQ[r][c4 * 4 + 0] = to_tf32(v.x);
            sQ[r][c4 * 4 + 1] = to_tf32(v.y);
            sQ[r][c4 * 4 + 2] = to_tf32(v.z);
            sQ[r][c4 * 4 + 3] = to_tf32(v.w);
        }
#pragma unroll
        for (int i = 0; i < 8; i++) {
            int idx = tid + i * 128;             // 0..1023
            int r = idx >> 3, c4 = idx & 7;
            float4 v = *(const float4*)(xb + (size_t)(tok0 + r) * HIDDEN + k0 + c4 * 4);
            sX[r][c4 * 4 + 0] = to_tf32(v.x);
            sX[r][c4 * 4 + 1] = to_tf32(v.y);
            sX[r][c4 * 4 + 2] = to_tf32(v.z);
            sX[r][c4 * 4 + 3] = to_tf32(v.w);
        }
        __syncthreads();
#pragma unroll
        for (int ks = 0; ks < 4; ks++) {
            int kk = ks * 8;
            uint32_t a[3][4], bb[4][2];
#pragma unroll
            for (int m = 0; m < 3; m++) {
                a[m][0] = __float_as_uint(sQ[m * 16 + g][kk + t]);
                a[m][1] = __float_as_uint(sQ[m * 16 + g + 8][kk + t]);
                a[m][2] = __float_as_uint(sQ[m * 16 + g][kk + t + 4]);
                a[m][3] = __float_as_uint(sQ[m * 16 + g + 8][kk + t + 4]);
            }
#pragma unroll
            for (int n = 0; n < 4; n++) {
                bb[n][0] = __float_as_uint(sX[warp * 32 + n * 8 + g][kk + t]);
                bb[n][1] = __float_as_uint(sX[warp * 32 + n * 8 + g][kk + t + 4]);
            }
#pragma unroll
            for (int m = 0; m < 3; m++)
#pragma unroll
                for (int n = 0; n < 4; n++) mma_tf32(acc[m][n], a[m], bb[n]);
        }
        __syncthreads();
    }
#pragma unroll
    for (int m = 0; m < 3; m++)
#pragma unroll
        for (int n = 0; n < 4; n++) {
            int r = m * 16 + g;
            int col = tok0 + warp * 32 + n * 8 + t * 2;
            float2 v0 = make_float2(acc[m][n][0], acc[m][n][1]);
            float2 v1 = make_float2(acc[m][n][2], acc[m][n][3]);
            *(float2*)(g_logits + ((size_t)b * NROW + r) * SEQ + col) = v0;
            *(float2*)(g_logits + ((size_t)b * NROW + r + 8) * SEQ + col) = v1;
        }
}

// ---------------- K4: rowwise max + 1/sum(exp) -----------------------------
__global__ void __launch_bounds__(256) k_rowstats() {
    int row = blockIdx.x;   // 0..383
    const float* lp = g_logits + (size_t)row * SEQ;
    int tid = threadIdx.x;
    float m = -3.4e38f;
    for (int i = tid; i < SEQ; i += 256) m = fmaxf(m, lp[i]);
    __shared__ float red[8];
    __shared__ float red2[8];
#pragma unroll
    for (int o = 16; o > 0; o >>= 1) m = fmaxf(m, __shfl_xor_sync(0xffffffffu, m, o));
    if ((tid & 31) == 0) red[tid >> 5] = m;
    __syncthreads();
    if (tid == 0) {
        float v = red[0];
        for (int i = 1; i < 8; i++) v = fmaxf(v, red[i]);
        red[0] = v;
    }
    __syncthreads();
    m = red[0];
    float s = 0.f;
    for (int i = tid; i < SEQ; i += 256) s += __expf(lp[i] - m);
#pragma unroll
    for (int o = 16; o > 0; o >>= 1) s += __shfl_xor_sync(0xffffffffu, s, o);
    if ((tid & 31) == 0) red2[tid >> 5] = s;
    __syncthreads();
    if (tid == 0) {
        float v = 0.f;
        for (int i = 0; i < 8; i++) v += red2[i];
        g_rowmax[row] = m;
        g_rowinv[row] = 1.0f / v;
    }
}

// ---------------- K5: ctx partials = softmax(logits) @ x (tf32 mma) --------
// grid (6 ntile, 8 kchunk, 8 b), 128 thr. Tile: M=48, N=128 cols, K=1024 tokens.
__global__ void __launch_bounds__(128) k_ctx(const float* __restrict__ x) {
    int nt = blockIdx.x;
    int kc = blockIdx.y;
    int b = blockIdx.z;
    int tid = threadIdx.x;
    int warp = tid >> 5, lane = tid & 31;
    int g = lane >> 2, t = lane & 3;
    __shared__ float sA[48][36];
    __shared__ float sX[32][136];
    float acc[3][4][4];
#pragma unroll
    for (int m = 0; m < 3; m++)
#pragma unroll
        for (int n = 0; n < 4; n++)
#pragma unroll
            for (int i = 0; i < 4; i++) acc[m][n][i] = 0.f;

    float rm[12], ri[12];
#pragma unroll
    for (int i = 0; i < 12; i++) {
        int r = (tid + i * 128) >> 5;
        rm[i] = g_rowmax[b * NROW + r];
        ri[i] = g_rowinv[b * NROW + r];
    }
    int tokbase = kc * TOK_PER_KC;
    for (int sc = 0; sc < TOK_PER_KC / 32; sc++) {
        int tok0 = tokbase + sc * 32;
#pragma unroll
        for (int i = 0; i < 12; i++) {
            int idx = tid + i * 128;
            int r = idx >> 5, tl = idx & 31;
            float l = g_logits[((size_t)b * NROW + r) * SEQ + tok0 + tl];
            sA[r][tl] = to_tf32(__expf(l - rm[i]) * ri[i]);
        }
#pragma unroll
        for (int i = 0; i < 8; i++) {
            int idx = tid + i * 128;                // 0..1023
            int r = idx >> 5, c4 = idx & 31;        // 32 float4 per token row
            float4 v = *(const float4*)(x + ((size_t)b * SEQ + tok0 + r) * HIDDEN + nt * 128 + c4 * 4);
            sX[r][c4 * 4 + 0] = to_tf32(v.x);
            sX[r][c4 * 4 + 1] = to_tf32(v.y);
            sX[r][c4 * 4 + 2] = to_tf32(v.z);
            sX[r][c4 * 4 + 3] = to_tf32(v.w);
        }
        __syncthreads();
#pragma unroll
        for (int ks = 0; ks < 4; ks++) {
            int kk = ks * 8;
            uint32_t a[3][4], bb[4][2];
#pragma unroll
            for (int m = 0; m < 3; m++) {
                a[m][0] = __float_as_uint(sA[m * 16 + g][kk + t]);
                a[m][1] = __float_as_uint(sA[m * 16 + g + 8][kk + t]);
                a[m][2] = __float_as_uint(sA[m * 16 + g][kk + t + 4]);
                a[m][3] = __float_as_uint(sA[m * 16 + g + 8][kk + t + 4]);
            }
#pragma unroll
            for (int n = 0; n < 4; n++) {
                bb[n][0] = __float_as_uint(sX[kk + t][warp * 32 + n * 8 + g]);
                bb[n][1] = __float_as_uint(sX[kk + t + 4][warp * 32 + n * 8 + g]);
            }
#pragma unroll
            for (int m = 0; m < 3; m++)
#pragma unroll
                for (int n = 0; n < 4; n++) mma_tf32(acc[m][n], a[m], bb[n]);
        }
        __syncthreads();
    }
#pragma unroll
    for (int m = 0; m < 3; m++)
#pragma unroll
        for (int n = 0; n < 4; n++) {
            int r = m * 16 + g;
            int col = nt * 128 + warp * 32 + n * 8 + t * 2;
            size_t base = ((size_t)kc * (BATCH * NROW) + b * NROW + r) * HIDDEN + col;
            *(float2*)(g_ctxp + base) = make_float2(acc[m][n][0], acc[m][n][1]);
            *(float2*)(g_ctxp + base + (size_t)8 * HIDDEN) = make_float2(acc[m][n][2], acc[m][n][3]);
        }
}

// ---------------- K6: o2[b,x,h*64+d] = ctx_row . Wv_h[d,:]  ----------------
// grid (12 h, 8 b), 256 thr. Also reduces the 8 ctx partials.
__global__ void __launch_bounds__(256) k_out1(const float* __restrict__ wkv) {
    int h = blockIdx.x, b = blockIdx.y;
    __shared__ float sC[4][64];
    __shared__ float sW[64][65];
    int tid = threadIdx.x;
    int xx = tid >> 6, d = tid & 63;
    float acc = 0.f;
    for (int j0 = 0; j0 < HIDDEN; j0 += 64) {
        __syncthreads();
        {
            float v = 0.f;
#pragma unroll
            for (int kc = 0; kc < KCH_CTX; kc++)
                v += g_ctxp[((size_t)kc * (BATCH * NROW) + b * NROW + h * 4 + xx) * HIDDEN + j0 + d];
            sC[xx][d] = v;
        }
        for (int i = tid; i < 64 * 64; i += 256) {
            int r = i >> 6, c = i & 63;
            sW[r][c] = wkv[(size_t)(HIDDEN + h * 64 + r) * HIDDEN + j0 + c];
        }
        __syncthreads();
#pragma unroll
        for (int jj = 0; jj < 64; jj++) acc += sC[xx][jj] * sW[d][jj];
    }
    g_o[(size_t)(b * 4 + xx) * HIDDEN + h * 64 + d] = acc;
}

// ---------------- K7: out = o2 @ w_out^T + b_out ---------------------------
// grid (3 etile, 8 b), 256 thr
__global__ void __launch_bounds__(256) k_out2(const float* __restrict__ wout,
                                              const float* __restrict__ bout,
                                              float* __restrict__ out) {
    int e0 = blockIdx.x * 256, b = blockIdx.y;
    __shared__ float sO[4][HIDDEN];
    __shared__ float sW[256][33];
    int tid = threadIdx.x;
    for (int i = tid; i < 4 * HIDDEN; i += 256) {
        int r = i / HIDDEN, c = i % HIDDEN;
        sO[r][c] = g_o[(size_t)(b * 4 + r) * HIDDEN + c];
    }
    float a0 = 0.f, a1 = 0.f, a2 = 0.f, a3 = 0.f;
    for (int kc = 0; kc < 24; kc++) {
        int k0 = kc * 32;
        __syncthreads();
        for (int i = tid; i < 256 * 32; i += 256) {
            int r = i >> 5, c = i & 31;
            sW[r][c] = wout[(size_t)(e0 + r) * HIDDEN + k0 + c];
        }
        __syncthreads();
#pragma unroll
        for (int kk = 0; kk < 32; kk++) {
            float w = sW[tid][kk];
            a0 += sO[0][k0 + kk] * w;
            a1 += sO[1][k0 + kk] * w;
            a2 += sO[2][k0 + kk] * w;
            a3 += sO[3][k0 + kk] * w;
        }
    }
    float bb = bout[e0 + tid];
    out[(size_t)(b * 4 + 0) * HIDDEN + e0 + tid] = a0 + bb;
    out[(size_t)(b * 4 + 1) * HIDDEN + e0 + tid] = a1 + bb;
    out[(size_t)(b * 4 + 2) * HIDDEN + e0 + tid] = a2 + bb;
    out[(size_t)(b * 4 + 3) * HIDDEN + e0 + tid] = a3 + bb;
}

// ---------------- entry -----------------------------------------------------
extern "C" void kernel_launch(void* const* d_in, const int* in_sizes, int n_in,
                              void* d_out, int out_size) {
    const float* x     = (const float*)d_in[0];  // [8, 8192, 768]
    const float* w_kv  = (const float*)d_in[1];  // [1536, 768]
    const float* w_q   = (const float*)d_in[2];  // [768, 768]
    const float* w_out = (const float*)d_in[3];  // [768, 768]
    const float* b_out = (const float*)d_in[4];  // [768]
    float* out = (float*)d_out;                  // [8, 4, 768]

    k_qproj<<<dim3(6, 8), 256>>>(x, w_q);
    k_qk<<<dim3(12, 8), 256>>>(w_kv);
    k_logits<<<dim3(64, 8), 128>>>(x);
    k_rowstats<<<BATCH * NROW, 256>>>();
    k_ctx<<<dim3(6, KCH_CTX, 8), 128>>>(x);
    k_out1<<<dim3(12, 8), 256>>>(w_kv);
    k_out2<<<dim3(3, 8), 256>>>(w_out, b_out, out);
}

// round 2
// speedup vs baseline: 1.0970x; 1.0970x over previous
#include <cuda_runtime.h>
#include <cuda_bf16.h>
#include <cstdint>

#define NUM_HEADS 12
#define NUM_BN 4
#define HIDDEN 768
#define HEAD_DIM 64
#define BATCH 8
#define SEQ 8192
#define NROW 48            // NUM_HEADS * NUM_BN per batch
#define SCALE 0.125f       // 64^-0.5
#define KCH_CTX 8          // k-split chunks for ctx pass
#define TOK_PER_KC (SEQ / KCH_CTX)   // 1024

// ---------------- scratch (static device memory; no allocs allowed) -------
__device__ float g_q[BATCH * NUM_BN * HIDDEN];
__device__ float g_qk[BATCH * NROW * HIDDEN];
__device__ float g_logits[(size_t)BATCH * NROW * SEQ];            // logits -> probs (in place)
__device__ float g_ctxp[(size_t)KCH_CTX * BATCH * NROW * HIDDEN];
__device__ float g_o[BATCH * NUM_BN * HIDDEN];

// ---------------- helpers -------------------------------------------------
__device__ __forceinline__ float to_tf32(float v) {
    uint32_t u;
    asm("cvt.rna.tf32.f32 %0, %1;" : "=r"(u) : "f"(v));
    return __uint_as_float(u);
}
__device__ __forceinline__ uint32_t tf32b(float v) {
    uint32_t u;
    asm("cvt.rna.tf32.f32 %0, %1;" : "=r"(u) : "f"(v));
    return u;
}
__device__ __forceinline__ void mma_tf32(float* d, const uint32_t* a, const uint32_t* b) {
    asm volatile(
        "mma.sync.aligned.m16n8k8.row.col.f32.tf32.tf32.f32 "
        "{%0,%1,%2,%3}, {%4,%5,%6,%7}, {%8,%9}, {%0,%1,%2,%3};"
        : "+f"(d[0]), "+f"(d[1]), "+f"(d[2]), "+f"(d[3])
        : "r"(a[0]), "r"(a[1]), "r"(a[2]), "r"(a[3]), "r"(b[0]), "r"(b[1]));
}
__device__ __forceinline__ void cp16(float* dst_smem, const float* src_gmem) {
    uint32_t d = (uint32_t)__cvta_generic_to_shared(dst_smem);
    asm volatile("cp.async.cg.shared.global [%0], [%1], 16;" :: "r"(d), "l"(src_gmem));
}
__device__ __forceinline__ void cp_commit() { asm volatile("cp.async.commit_group;"); }
__device__ __forceinline__ void cp_wait1() { asm volatile("cp.async.wait_group 1;"); }
__device__ __forceinline__ void cp_wait0() { asm volatile("cp.async.wait_group 0;"); }

// ---------------- K1: q = x[:, :4] @ w_q^T --------------------------------
__global__ void __launch_bounds__(256) k_qproj(const float* __restrict__ x,
                                               const float* __restrict__ wq) {
    __shared__ float sX[4][HIDDEN];
    __shared__ float sW[128][65];
    int b = blockIdx.y, o0 = blockIdx.x * 128;
    int tid = threadIdx.x;
    for (int i = tid; i < 4 * HIDDEN; i += 256) {
        int r = i / HIDDEN, c = i % HIDDEN;
        sX[r][c] = x[((size_t)b * SEQ + r) * HIDDEN + c];
    }
    int ol = tid & 127, xp = tid >> 7;
    float acc0 = 0.f, acc1 = 0.f;
    for (int kc = 0; kc < 12; kc++) {
        int k0 = kc * 64;
        __syncthreads();
        for (int i = tid; i < 128 * 64; i += 256) {
            int r = i >> 6, c = i & 63;
            sW[r][c] = wq[(size_t)(o0 + r) * HIDDEN + k0 + c];
        }
        __syncthreads();
#pragma unroll 8
        for (int kk = 0; kk < 64; kk++) {
            float w = sW[ol][kk];
            acc0 += sX[xp * 2][k0 + kk] * w;
            acc1 += sX[xp * 2 + 1][k0 + kk] * w;
        }
    }
    g_q[(size_t)(b * 4 + xp * 2) * HIDDEN + o0 + ol] = acc0;
    g_q[(size_t)(b * 4 + xp * 2 + 1) * HIDDEN + o0 + ol] = acc1;
}

// ---------------- K2: qk = SCALE * q_h @ Wk_h, tf32-pre-rounded -----------
__global__ void __launch_bounds__(256) k_qk(const float* __restrict__ wkv) {
    int h = blockIdx.x, b = blockIdx.y;
    __shared__ float sQ[4][64];
    __shared__ float sW[32][257];
    int tid = threadIdx.x;
    {
        int xx = tid >> 6, d = tid & 63;
        sQ[xx][d] = g_q[(size_t)(b * 4 + xx) * HIDDEN + h * 64 + d];
    }
    for (int n0 = 0; n0 < HIDDEN; n0 += 256) {
        float a0 = 0.f, a1 = 0.f, a2 = 0.f, a3 = 0.f;
        for (int kc = 0; kc < 2; kc++) {
            __syncthreads();
            for (int i = tid; i < 32 * 256; i += 256) {
                int r = i >> 8, c = i & 255;
                sW[r][c] = wkv[(size_t)(h * 64 + kc * 32 + r) * HIDDEN + n0 + c];
            }
            __syncthreads();
#pragma unroll
            for (int d = 0; d < 32; d++) {
                float w = sW[d][tid];
                int kd = kc * 32 + d;
                a0 += sQ[0][kd] * w;
                a1 += sQ[1][kd] * w;
                a2 += sQ[2][kd] * w;
                a3 += sQ[3][kd] * w;
            }
        }
        size_t rb = (size_t)(b * NROW + h * 4) * HIDDEN + n0 + tid;
        g_qk[rb] = to_tf32(a0 * SCALE);
        g_qk[rb + HIDDEN] = to_tf32(a1 * SCALE);
        g_qk[rb + 2 * HIDDEN] = to_tf32(a2 * SCALE);
        g_qk[rb + 3 * HIDDEN] = to_tf32(a3 * SCALE);
    }
}

// ---------------- K3: logits = qk @ x^T, pipelined tf32 mma ---------------
// grid (32 token-tiles, 8 b), 256 thr (8 warps). Tile M=48, N=256, K=768.
// smem: sQ[2][48][36] + sX[2][256][36]  (dynamic, 87.5 KB)
#define LQ_OFF 0
#define LX_OFF (2 * 48 * 36)
__global__ void __launch_bounds__(256) k_logits(const float* __restrict__ x) {
    extern __shared__ float sm[];
    int b = blockIdx.y;
    int tok0 = blockIdx.x * 256;
    int tid = threadIdx.x;
    int warp = tid >> 5, lane = tid & 31;
    int g = lane >> 2, t = lane & 3;
    const float* xb = x + (size_t)b * SEQ * HIDDEN;
    const float* qb = g_qk + (size_t)b * NROW * HIDDEN;

    float acc[3][4][4];
#pragma unroll
    for (int m = 0; m < 3; m++)
#pragma unroll
        for (int n = 0; n < 4; n++)
#pragma unroll
            for (int i = 0; i < 4; i++) acc[m][n][i] = 0.f;

    // stage chunk kc into buffer s
    auto stage = [&](int kc, int s) {
        int k0 = kc * 32;
        float* q = sm + LQ_OFF + s * 48 * 36;
#pragma unroll
        for (int i = 0; i < 2; i++) {
            int idx = tid + i * 256;
            if (idx < 384) {
                int r = idx >> 3, c = (idx & 7) * 4;
                cp16(q + r * 36 + c, qb + (size_t)r * HIDDEN + k0 + c);
            }
        }
        float* xs = sm + LX_OFF + s * 256 * 36;
#pragma unroll
        for (int i = 0; i < 8; i++) {
            int idx = tid + i * 256;
            int r = idx >> 3, c = (idx & 7) * 4;
            cp16(xs + r * 36 + c, xb + (size_t)(tok0 + r) * HIDDEN + k0 + c);
        }
        cp_commit();
    };

    stage(0, 0);
    for (int kc = 0; kc < 24; kc++) {
        int s = kc & 1;
        if (kc + 1 < 24) {
            stage(kc + 1, s ^ 1);
            cp_wait1();
        } else {
            cp_wait0();
        }
        __syncthreads();
        const float* q = sm + LQ_OFF + s * 48 * 36;
        const float* xs = sm + LX_OFF + s * 256 * 36;
#pragma unroll
        for (int ks = 0; ks < 4; ks++) {
            int kk = ks * 8;
            uint32_t a[3][4], bb[4][2];
#pragma unroll
            for (int m = 0; m < 3; m++) {
                a[m][0] = __float_as_uint(q[(m * 16 + g) * 36 + kk + t]);
                a[m][1] = __float_as_uint(q[(m * 16 + g + 8) * 36 + kk + t]);
                a[m][2] = __float_as_uint(q[(m * 16 + g) * 36 + kk + t + 4]);
                a[m][3] = __float_as_uint(q[(m * 16 + g + 8) * 36 + kk + t + 4]);
            }
#pragma unroll
            for (int n = 0; n < 4; n++) {
                bb[n][0] = tf32b(xs[(warp * 32 + n * 8 + g) * 36 + kk + t]);
                bb[n][1] = tf32b(xs[(warp * 32 + n * 8 + g) * 36 + kk + t + 4]);
            }
#pragma unroll
            for (int m = 0; m < 3; m++)
#pragma unroll
                for (int n = 0; n < 4; n++) mma_tf32(acc[m][n], a[m], bb[n]);
        }
        __syncthreads();
    }
#pragma unroll
    for (int m = 0; m < 3; m++)
#pragma unroll
        for (int n = 0; n < 4; n++) {
            int r = m * 16 + g;
            int col = tok0 + warp * 32 + n * 8 + t * 2;
            *(float2*)(g_logits + ((size_t)b * NROW + r) * SEQ + col) =
                make_float2(acc[m][n][0], acc[m][n][1]);
            *(float2*)(g_logits + ((size_t)b * NROW + r + 8) * SEQ + col) =
                make_float2(acc[m][n][2], acc[m][n][3]);
        }
}

// ---------------- K4: softmax in place: logits -> tf32 probs --------------
// 384 blocks x 256 thr. 32 values per thread held in registers.
__global__ void __launch_bounds__(256) k_rowstats() {
    int row = blockIdx.x;
    float* lp = g_logits + (size_t)row * SEQ;
    int tid = threadIdx.x;
    float4 v[8];
#pragma unroll
    for (int i = 0; i < 8; i++) v[i] = ((const float4*)lp)[i * 256 + tid];

    float m = -3.4e38f;
#pragma unroll
    for (int i = 0; i < 8; i++) {
        m = fmaxf(m, fmaxf(fmaxf(v[i].x, v[i].y), fmaxf(v[i].z, v[i].w)));
    }
    __shared__ float red[8];
#pragma unroll
    for (int o = 16; o > 0; o >>= 1) m = fmaxf(m, __shfl_xor_sync(0xffffffffu, m, o));
    if ((tid & 31) == 0) red[tid >> 5] = m;
    __syncthreads();
    if (tid < 32) {
        float v2 = (tid < 8) ? red[tid] : -3.4e38f;
#pragma unroll
        for (int o = 4; o > 0; o >>= 1) v2 = fmaxf(v2, __shfl_xor_sync(0xffffffffu, v2, o));
        if (tid == 0) red[0] = v2;
    }
    __syncthreads();
    m = red[0];

    float s = 0.f;
#pragma unroll
    for (int i = 0; i < 8; i++) {
        v[i].x = __expf(v[i].x - m);
        v[i].y = __expf(v[i].y - m);
        v[i].z = __expf(v[i].z - m);
        v[i].w = __expf(v[i].w - m);
        s += (v[i].x + v[i].y) + (v[i].z + v[i].w);
    }
    __shared__ float red2[8];
#pragma unroll
    for (int o = 16; o > 0; o >>= 1) s += __shfl_xor_sync(0xffffffffu, s, o);
    if ((tid & 31) == 0) red2[tid >> 5] = s;
    __syncthreads();
    if (tid < 32) {
        float v2 = (tid < 8) ? red2[tid] : 0.f;
#pragma unroll
        for (int o = 4; o > 0; o >>= 1) v2 += __shfl_xor_sync(0xffffffffu, v2, o);
        if (tid == 0) red2[0] = v2;
    }
    __syncthreads();
    float inv = 1.0f / red2[0];

#pragma unroll
    for (int i = 0; i < 8; i++) {
        float4 p;
        p.x = to_tf32(v[i].x * inv);
        p.y = to_tf32(v[i].y * inv);
        p.z = to_tf32(v[i].z * inv);
        p.w = to_tf32(v[i].w * inv);
        ((float4*)lp)[i * 256 + tid] = p;
    }
}

// ---------------- K5: ctx partials = probs @ x, pipelined tf32 mma --------
// grid (3 ntile, 8 kchunk, 8 b), 256 thr. Tile M=48, N=256 cols, K=1024 tokens.
// smem: sA[2][48][36] + sX[2][32][264]  (dynamic, 81.4 KB)
#define CA_OFF 0
#define CX_OFF (2 * 48 * 36)
__global__ void __launch_bounds__(256) k_ctx(const float* __restrict__ x) {
    extern __shared__ float sm[];
    int nt = blockIdx.x;
    int kc = blockIdx.y;
    int b = blockIdx.z;
    int tid = threadIdx.x;
    int warp = tid >> 5, lane = tid & 31;
    int g = lane >> 2, t = lane & 3;
    int tokbase = kc * TOK_PER_KC;
    const float* pb = g_logits + (size_t)b * NROW * SEQ;
    const float* xb = x + ((size_t)b * SEQ) * HIDDEN + nt * 256;

    float acc[3][4][4];
#pragma unroll
    for (int m = 0; m < 3; m++)
#pragma unroll
        for (int n = 0; n < 4; n++)
#pragma unroll
            for (int i = 0; i < 4; i++) acc[m][n][i] = 0.f;

    auto stage = [&](int ch, int s) {
        int tok0 = tokbase + ch * 32;
        float* a = sm + CA_OFF + s * 48 * 36;
#pragma unroll
        for (int i = 0; i < 2; i++) {
            int idx = tid + i * 256;
            if (idx < 384) {
                int r = idx >> 3, c = (idx & 7) * 4;
                cp16(a + r * 36 + c, pb + (size_t)r * SEQ + tok0 + c);
            }
        }
        float* xs = sm + CX_OFF + s * 32 * 264;
#pragma unroll
        for (int i = 0; i < 8; i++) {
            int idx = tid + i * 256;
            int r = idx >> 6, c = (idx & 63) * 4;
            cp16(xs + r * 264 + c, xb + (size_t)(tok0 + r) * HIDDEN + c);
        }
        cp_commit();
    };

    const int NCH = TOK_PER_KC / 32;   // 32 chunks
    stage(0, 0);
    for (int ch = 0; ch < NCH; ch++) {
        int s = ch & 1;
        if (ch + 1 < NCH) {
            stage(ch + 1, s ^ 1);
            cp_wait1();
        } else {
            cp_wait0();
        }
        __syncthreads();
        const float* a = sm + CA_OFF + s * 48 * 36;
        const float* xs = sm + CX_OFF + s * 32 * 264;
#pragma unroll
        for (int ks = 0; ks < 4; ks++) {
            int kk = ks * 8;
            uint32_t af[3][4], bb[4][2];
#pragma unroll
            for (int m = 0; m < 3; m++) {
                af[m][0] = __float_as_uint(a[(m * 16 + g) * 36 + kk + t]);
                af[m][1] = __float_as_uint(a[(m * 16 + g + 8) * 36 + kk + t]);
                af[m][2] = __float_as_uint(a[(m * 16 + g) * 36 + kk + t + 4]);
                af[m][3] = __float_as_uint(a[(m * 16 + g + 8) * 36 + kk + t + 4]);
            }
#pragma unroll
            for (int n = 0; n < 4; n++) {
                bb[n][0] = tf32b(xs[(kk + t) * 264 + warp * 32 + n * 8 + g]);
                bb[n][1] = tf32b(xs[(kk + t + 4) * 264 + warp * 32 + n * 8 + g]);
            }
#pragma unroll
            for (int m = 0; m < 3; m++)
#pragma unroll
                for (int n = 0; n < 4; n++) mma_tf32(acc[m][n], af[m], bb[n]);
        }
        __syncthreads();
    }
#pragma unroll
    for (int m = 0; m < 3; m++)
#pragma unroll
        for (int n = 0; n < 4; n++) {
            int r = m * 16 + g;
            int col = nt * 256 + warp * 32 + n * 8 + t * 2;
            size_t base = ((size_t)(kc * BATCH + b) * NROW + r) * HIDDEN + col;
            *(float2*)(g_ctxp + base) = make_float2(acc[m][n][0], acc[m][n][1]);
            *(float2*)(g_ctxp + base + (size_t)8 * HIDDEN) =
                make_float2(acc[m][n][2], acc[m][n][3]);
        }
}

// ---------------- K6: o = sum_kc(ctxp) @ Wv_h^T per head -------------------
__global__ void __launch_bounds__(256) k_out1(const float* __restrict__ wkv) {
    int h = blockIdx.x, b = blockIdx.y;
    __shared__ float sC[4][64];
    __shared__ float sW[64][65];
    int tid = threadIdx.x;
    int xx = tid >> 6, d = tid & 63;
    float acc = 0.f;
    for (int j0 = 0; j0 < HIDDEN; j0 += 64) {
        __syncthreads();
        {
            float v = 0.f;
#pragma unroll
            for (int kc = 0; kc < KCH_CTX; kc++)
                v += g_ctxp[((size_t)(kc * BATCH + b) * NROW + h * 4 + xx) * HIDDEN + j0 + d];
            sC[xx][d] = v;
        }
        for (int i = tid; i < 64 * 64; i += 256) {
            int r = i >> 6, c = i & 63;
            sW[r][c] = wkv[(size_t)(HIDDEN + h * 64 + r) * HIDDEN + j0 + c];
        }
        __syncthreads();
#pragma unroll
        for (int jj = 0; jj < 64; jj++) acc += sC[xx][jj] * sW[d][jj];
    }
    g_o[(size_t)(b * 4 + xx) * HIDDEN + h * 64 + d] = acc;
}

// ---------------- K7: out = o @ w_out^T + b_out ----------------------------
__global__ void __launch_bounds__(256) k_out2(const float* __restrict__ wout,
                                              const float* __restrict__ bout,
                                              float* __restrict__ out) {
    int e0 = blockIdx.x * 256, b = blockIdx.y;
    __shared__ float sO[4][HIDDEN];
    __shared__ float sW[256][33];
    int tid = threadIdx.x;
    for (int i = tid; i < 4 * HIDDEN; i += 256) {
        int r = i / HIDDEN, c = i % HIDDEN;
        sO[r][c] = g_o[(size_t)(b * 4 + r) * HIDDEN + c];
    }
    float a0 = 0.f, a1 = 0.f, a2 = 0.f, a3 = 0.f;
    for (int kc = 0; kc < 24; kc++) {
        int k0 = kc * 32;
        __syncthreads();
        for (int i = tid; i < 256 * 32; i += 256) {
            int r = i >> 5, c = i & 31;
            sW[r][c] = wout[(size_t)(e0 + r) * HIDDEN + k0 + c];
        }
        __syncthreads();
#pragma unroll
        for (int kk = 0; kk < 32; kk++) {
            float w = sW[tid][kk];
            a0 += sO[0][k0 + kk] * w;
            a1 += sO[1][k0 + kk] * w;
            a2 += sO[2][k0 + kk] * w;
            a3 += sO[3][k0 + kk] * w;
        }
    }
    float bb = bout[e0 + tid];
    out[(size_t)(b * 4 + 0) * HIDDEN + e0 + tid] = a0 + bb;
    out[(size_t)(b * 4 + 1) * HIDDEN + e0 + tid] = a1 + bb;
    out[(size_t)(b * 4 + 2) * HIDDEN + e0 + tid] = a2 + bb;
    out[(size_t)(b * 4 + 3) * HIDDEN + e0 + tid] = a3 + bb;
}

// ---------------- entry -----------------------------------------------------
extern "C" void kernel_launch(void* const* d_in, const int* in_sizes, int n_in,
                              void* d_out, int out_size) {
    const float* x     = (const float*)d_in[0];  // [8, 8192, 768]
    const float* w_kv  = (const float*)d_in[1];  // [1536, 768]
    const float* w_q   = (const float*)d_in[2];  // [768, 768]
    const float* w_out = (const float*)d_in[3];  // [768, 768]
    const float* b_out = (const float*)d_in[4];  // [768]
    float* out = (float*)d_out;                  // [8, 4, 768]

    const int smem_logits = (2 * 48 * 36 + 2 * 256 * 36) * 4;  // 87552 B
    const int smem_ctx    = (2 * 48 * 36 + 2 * 32 * 264) * 4;  // 81408 B
    cudaFuncSetAttribute(k_logits, cudaFuncAttributeMaxDynamicSharedMemorySize, smem_logits);
    cudaFuncSetAttribute(k_ctx, cudaFuncAttributeMaxDynamicSharedMemorySize, smem_ctx);

    k_qproj<<<dim3(6, 8), 256>>>(x, w_q);
    k_qk<<<dim3(12, 8), 256>>>(w_kv);
    k_logits<<<dim3(32, 8), 256, smem_logits>>>(x);
    k_rowstats<<<BATCH * NROW, 256>>>();
    k_ctx<<<dim3(3, KCH_CTX, 8), 256, smem_ctx>>>(x);
    k_out1<<<dim3(12, 8), 256>>>(w_kv);
    k_out2<<<dim3(3, 8), 256>>>(w_out, b_out, out);
}

// round 3
// speedup vs baseline: 1.1342x; 1.0339x over previous
#include <cuda_runtime.h>
#include <cuda_fp16.h>
#include <cstdint>

#define NUM_HEADS 12
#define NUM_BN 4
#define HIDDEN 768
#define HEAD_DIM 64
#define BATCH 8
#define SEQ 8192
#define NROW 48
#define SCALE 0.125f
#define KCH_CTX 8
#define TOK_PER_KC (SEQ / KCH_CTX)   // 1024

// ---------------- scratch -------------------------------------------------
__device__ float  g_q[BATCH * NUM_BN * HIDDEN];
__device__ __half g_qk[BATCH * NROW * HIDDEN];                     // fp16 pre-scaled
__device__ float  g_logits[(size_t)BATCH * NROW * SEQ];            // fp32 logits
__device__ __half g_probs[(size_t)BATCH * NROW * SEQ];             // fp16 probs
__device__ float  g_ctxp[(size_t)KCH_CTX * BATCH * NROW * HIDDEN];
__device__ float  g_o[BATCH * NUM_BN * HIDDEN];

// ---------------- helpers -------------------------------------------------
__device__ __forceinline__ void mma_f16(float* d, const uint32_t* a, const uint32_t* b) {
    asm volatile(
        "mma.sync.aligned.m16n8k16.row.col.f32.f16.f16.f32 "
        "{%0,%1,%2,%3}, {%4,%5,%6,%7}, {%8,%9}, {%0,%1,%2,%3};"
        : "+f"(d[0]), "+f"(d[1]), "+f"(d[2]), "+f"(d[3])
        : "r"(a[0]), "r"(a[1]), "r"(a[2]), "r"(a[3]), "r"(b[0]), "r"(b[1]));
}
__device__ __forceinline__ uint32_t packh2(float lo, float hi) {
    uint32_t r;
    asm("cvt.rn.f16x2.f32 %0, %1, %2;" : "=r"(r) : "f"(hi), "f"(lo));
    return r;
}
__device__ __forceinline__ void cp16(void* dst_smem, const void* src_gmem) {
    uint32_t d = (uint32_t)__cvta_generic_to_shared(dst_smem);
    asm volatile("cp.async.cg.shared.global [%0], [%1], 16;" :: "r"(d), "l"(src_gmem));
}
__device__ __forceinline__ void cp_commit() { asm volatile("cp.async.commit_group;"); }
__device__ __forceinline__ void cp_wait1() { asm volatile("cp.async.wait_group 1;"); }
__device__ __forceinline__ void cp_wait0() { asm volatile("cp.async.wait_group 0;"); }

// ---------------- K1: q = x[:, :4] @ w_q^T --------------------------------
__global__ void __launch_bounds__(256) k_qproj(const float* __restrict__ x,
                                               const float* __restrict__ wq) {
    __shared__ float sX[4][HIDDEN];
    __shared__ float sW[128][65];
    int b = blockIdx.y, o0 = blockIdx.x * 128;
    int tid = threadIdx.x;
    for (int i = tid; i < 4 * HIDDEN; i += 256) {
        int r = i / HIDDEN, c = i % HIDDEN;
        sX[r][c] = x[((size_t)b * SEQ + r) * HIDDEN + c];
    }
    int ol = tid & 127, xp = tid >> 7;
    float acc0 = 0.f, acc1 = 0.f;
    for (int kc = 0; kc < 12; kc++) {
        int k0 = kc * 64;
        __syncthreads();
        for (int i = tid; i < 128 * 64; i += 256) {
            int r = i >> 6, c = i & 63;
            sW[r][c] = wq[(size_t)(o0 + r) * HIDDEN + k0 + c];
        }
        __syncthreads();
#pragma unroll 8
        for (int kk = 0; kk < 64; kk++) {
            float w = sW[ol][kk];
            acc0 += sX[xp * 2][k0 + kk] * w;
            acc1 += sX[xp * 2 + 1][k0 + kk] * w;
        }
    }
    g_q[(size_t)(b * 4 + xp * 2) * HIDDEN + o0 + ol] = acc0;
    g_q[(size_t)(b * 4 + xp * 2 + 1) * HIDDEN + o0 + ol] = acc1;
}

// ---------------- K2: qk = SCALE * q_h @ Wk_h -> fp16 ----------------------
__global__ void __launch_bounds__(256) k_qk(const float* __restrict__ wkv) {
    int h = blockIdx.x, b = blockIdx.y;
    __shared__ float sQ[4][64];
    __shared__ float sW[32][257];
    int tid = threadIdx.x;
    {
        int xx = tid >> 6, d = tid & 63;
        sQ[xx][d] = g_q[(size_t)(b * 4 + xx) * HIDDEN + h * 64 + d];
    }
    for (int n0 = 0; n0 < HIDDEN; n0 += 256) {
        float a0 = 0.f, a1 = 0.f, a2 = 0.f, a3 = 0.f;
        for (int kc = 0; kc < 2; kc++) {
            __syncthreads();
            for (int i = tid; i < 32 * 256; i += 256) {
                int r = i >> 8, c = i & 255;
                sW[r][c] = wkv[(size_t)(h * 64 + kc * 32 + r) * HIDDEN + n0 + c];
            }
            __syncthreads();
#pragma unroll
            for (int d = 0; d < 32; d++) {
                float w = sW[d][tid];
                int kd = kc * 32 + d;
                a0 += sQ[0][kd] * w;
                a1 += sQ[1][kd] * w;
                a2 += sQ[2][kd] * w;
                a3 += sQ[3][kd] * w;
            }
        }
        size_t rb = (size_t)(b * NROW + h * 4) * HIDDEN + n0 + tid;
        g_qk[rb] = __float2half(a0 * SCALE);
        g_qk[rb + HIDDEN] = __float2half(a1 * SCALE);
        g_qk[rb + 2 * HIDDEN] = __float2half(a2 * SCALE);
        g_qk[rb + 3 * HIDDEN] = __float2half(a3 * SCALE);
    }
}

// ---------------- K3: logits = qk @ x^T, fp16 mma, pipelined ---------------
// grid (32 token-tiles, 8 b), 256 thr. Tile M=48, N=256, K=768 (chunks of 32).
// smem (u32 units): sQ 2x[48][20] half2 rows, sX 2x[256][36] fp32
#define LQ_ST 20
#define LX_ST 36
#define LQ_SZ (48 * LQ_ST)
#define LX_SZ (256 * LX_ST)
__global__ void __launch_bounds__(256) k_logits(const float* __restrict__ x) {
    extern __shared__ uint32_t sm32[];
    float* smf = (float*)sm32;
    int b = blockIdx.y;
    int tok0 = blockIdx.x * 256;
    int tid = threadIdx.x;
    int warp = tid >> 5, lane = tid & 31;
    int g = lane >> 2, t = lane & 3;
    const float* xb = x + (size_t)b * SEQ * HIDDEN;
    const __half* qb = g_qk + (size_t)b * NROW * HIDDEN;

    float acc[3][4][4];
#pragma unroll
    for (int m = 0; m < 3; m++)
#pragma unroll
        for (int n = 0; n < 4; n++)
#pragma unroll
            for (int i = 0; i < 4; i++) acc[m][n][i] = 0.f;

    auto stage = [&](int kc, int s) {
        int k0 = kc * 32;
        if (tid < 192) {
            int r = tid >> 2, c4 = tid & 3;   // 4x16B per 48 rows (32 halves)
            cp16(sm32 + s * LQ_SZ + r * LQ_ST + c4 * 4,
                 qb + (size_t)r * HIDDEN + k0 + c4 * 8);
        }
        uint32_t* xs = sm32 + 2 * LQ_SZ + s * LX_SZ;
#pragma unroll
        for (int i = 0; i < 8; i++) {
            int idx = tid + i * 256;
            int r = idx >> 3, c4 = idx & 7;
            cp16(xs + r * LX_ST + c4 * 4, xb + (size_t)(tok0 + r) * HIDDEN + k0 + c4 * 4);
        }
        cp_commit();
    };

    stage(0, 0);
    for (int kc = 0; kc < 24; kc++) {
        int s = kc & 1;
        if (kc + 1 < 24) { stage(kc + 1, s ^ 1); cp_wait1(); }
        else             { cp_wait0(); }
        __syncthreads();
        const uint32_t* q = sm32 + s * LQ_SZ;
        const float* xs = smf + 2 * LQ_SZ + s * LX_SZ;
#pragma unroll
        for (int ks = 0; ks < 2; ks++) {
            int kk = ks * 16, kk2 = ks * 8;
            uint32_t a[3][4], bb[4][2];
#pragma unroll
            for (int m = 0; m < 3; m++) {
                int r0 = m * 16 + g;
                a[m][0] = q[r0 * LQ_ST + kk2 + t];
                a[m][1] = q[(r0 + 8) * LQ_ST + kk2 + t];
                a[m][2] = q[r0 * LQ_ST + kk2 + t + 4];
                a[m][3] = q[(r0 + 8) * LQ_ST + kk2 + t + 4];
            }
#pragma unroll
            for (int n = 0; n < 4; n++) {
                int row = warp * 32 + n * 8 + g;
                float2 p0 = *(const float2*)(xs + row * LX_ST + kk + 2 * t);
                float2 p1 = *(const float2*)(xs + row * LX_ST + kk + 2 * t + 8);
                bb[n][0] = packh2(p0.x, p0.y);
                bb[n][1] = packh2(p1.x, p1.y);
            }
#pragma unroll
            for (int m = 0; m < 3; m++)
#pragma unroll
                for (int n = 0; n < 4; n++) mma_f16(acc[m][n], a[m], bb[n]);
        }
        __syncthreads();
    }
#pragma unroll
    for (int m = 0; m < 3; m++)
#pragma unroll
        for (int n = 0; n < 4; n++) {
            int r = m * 16 + g;
            int col = tok0 + warp * 32 + n * 8 + t * 2;
            *(float2*)(g_logits + ((size_t)b * NROW + r) * SEQ + col) =
                make_float2(acc[m][n][0], acc[m][n][1]);
            *(float2*)(g_logits + ((size_t)b * NROW + r + 8) * SEQ + col) =
                make_float2(acc[m][n][2], acc[m][n][3]);
        }
}

// ---------------- K4: softmax: fp32 logits -> fp16 probs -------------------
__global__ void __launch_bounds__(256) k_rowstats() {
    int row = blockIdx.x;
    const float* lp = g_logits + (size_t)row * SEQ;
    __half2* pp = (__half2*)(g_probs + (size_t)row * SEQ);
    int tid = threadIdx.x;
    float4 v[8];
#pragma unroll
    for (int i = 0; i < 8; i++) v[i] = ((const float4*)lp)[i * 256 + tid];

    float m = -3.4e38f;
#pragma unroll
    for (int i = 0; i < 8; i++)
        m = fmaxf(m, fmaxf(fmaxf(v[i].x, v[i].y), fmaxf(v[i].z, v[i].w)));
    __shared__ float red[8];
#pragma unroll
    for (int o = 16; o > 0; o >>= 1) m = fmaxf(m, __shfl_xor_sync(0xffffffffu, m, o));
    if ((tid & 31) == 0) red[tid >> 5] = m;
    __syncthreads();
    if (tid < 32) {
        float v2 = (tid < 8) ? red[tid] : -3.4e38f;
#pragma unroll
        for (int o = 4; o > 0; o >>= 1) v2 = fmaxf(v2, __shfl_xor_sync(0xffffffffu, v2, o));
        if (tid == 0) red[0] = v2;
    }
    __syncthreads();
    m = red[0];

    float s = 0.f;
#pragma unroll
    for (int i = 0; i < 8; i++) {
        v[i].x = __expf(v[i].x - m);
        v[i].y = __expf(v[i].y - m);
        v[i].z = __expf(v[i].z - m);
        v[i].w = __expf(v[i].w - m);
        s += (v[i].x + v[i].y) + (v[i].z + v[i].w);
    }
    __shared__ float red2[8];
#pragma unroll
    for (int o = 16; o > 0; o >>= 1) s += __shfl_xor_sync(0xffffffffu, s, o);
    if ((tid & 31) == 0) red2[tid >> 5] = s;
    __syncthreads();
    if (tid < 32) {
        float v2 = (tid < 8) ? red2[tid] : 0.f;
#pragma unroll
        for (int o = 4; o > 0; o >>= 1) v2 += __shfl_xor_sync(0xffffffffu, v2, o);
        if (tid == 0) red2[0] = v2;
    }
    __syncthreads();
    float inv = 1.0f / red2[0];

#pragma unroll
    for (int i = 0; i < 8; i++) {
        pp[(i * 256 + tid) * 2 + 0] = __floats2half2_rn(v[i].x * inv, v[i].y * inv);
        pp[(i * 256 + tid) * 2 + 1] = __floats2half2_rn(v[i].z * inv, v[i].w * inv);
    }
}

// ---------------- K5: ctx partials = probs @ x, fp16 mma, pipelined --------
// grid (3 ntile, 8 kchunk, 8 b), 256 thr. Tile M=48, N=256, K=1024 tokens.
// smem (u32): sA 2x[48][20] half2 rows, sX 2x[32][260] fp32
#define CA_ST 20
#define CX_ST 260
#define CA_SZ (48 * CA_ST)
#define CX_SZ (32 * CX_ST)
__global__ void __launch_bounds__(256) k_ctx(const float* __restrict__ x) {
    extern __shared__ uint32_t sm32[];
    float* smf = (float*)sm32;
    int nt = blockIdx.x;
    int kc = blockIdx.y;
    int b = blockIdx.z;
    int tid = threadIdx.x;
    int warp = tid >> 5, lane = tid & 31;
    int g = lane >> 2, t = lane & 3;
    int tokbase = kc * TOK_PER_KC;
    const __half* pb = g_probs + (size_t)b * NROW * SEQ;
    const float* xb = x + ((size_t)b * SEQ) * HIDDEN + nt * 256;

    float acc[3][4][4];
#pragma unroll
    for (int m = 0; m < 3; m++)
#pragma unroll
        for (int n = 0; n < 4; n++)
#pragma unroll
            for (int i = 0; i < 4; i++) acc[m][n][i] = 0.f;

    auto stage = [&](int ch, int s) {
        int tok0 = tokbase + ch * 32;
        if (tid < 192) {
            int r = tid >> 2, c4 = tid & 3;
            cp16(sm32 + s * CA_SZ + r * CA_ST + c4 * 4,
                 pb + (size_t)r * SEQ + tok0 + c4 * 8);
        }
        uint32_t* xs = sm32 + 2 * CA_SZ + s * CX_SZ;
#pragma unroll
        for (int i = 0; i < 8; i++) {
            int idx = tid + i * 256;
            int r = idx >> 6, c4 = idx & 63;
            cp16(xs + r * CX_ST + c4 * 4, xb + (size_t)(tok0 + r) * HIDDEN + c4 * 4);
        }
        cp_commit();
    };

    const int NCH = TOK_PER_KC / 32;   // 32
    stage(0, 0);
    for (int ch = 0; ch < NCH; ch++) {
        int s = ch & 1;
        if (ch + 1 < NCH) { stage(ch + 1, s ^ 1); cp_wait1(); }
        else              { cp_wait0(); }
        __syncthreads();
        const uint32_t* a = sm32 + s * CA_SZ;
        const float* xs = smf + 2 * CA_SZ + s * CX_SZ;
#pragma unroll
        for (int ks = 0; ks < 2; ks++) {
            int kk = ks * 16, kk2 = ks * 8;
            uint32_t af[3][4], bb[4][2];
#pragma unroll
            for (int m = 0; m < 3; m++) {
                int r0 = m * 16 + g;
                af[m][0] = a[r0 * CA_ST + kk2 + t];
                af[m][1] = a[(r0 + 8) * CA_ST + kk2 + t];
                af[m][2] = a[r0 * CA_ST + kk2 + t + 4];
                af[m][3] = a[(r0 + 8) * CA_ST + kk2 + t + 4];
            }
#pragma unroll
            for (int n = 0; n < 4; n++) {
                int col = warp * 32 + n * 8 + g;
                float f0 = xs[(kk + 2 * t) * CX_ST + col];
                float f1 = xs[(kk + 2 * t + 1) * CX_ST + col];
                float f2 = xs[(kk + 2 * t + 8) * CX_ST + col];
                float f3 = xs[(kk + 2 * t + 9) * CX_ST + col];
                bb[n][0] = packh2(f0, f1);
                bb[n][1] = packh2(f2, f3);
            }
#pragma unroll
            for (int m = 0; m < 3; m++)
#pragma unroll
                for (int n = 0; n < 4; n++) mma_f16(acc[m][n], af[m], bb[n]);
        }
        __syncthreads();
    }
#pragma unroll
    for (int m = 0; m < 3; m++)
#pragma unroll
        for (int n = 0; n < 4; n++) {
            int r = m * 16 + g;
            int col = nt * 256 + warp * 32 + n * 8 + t * 2;
            size_t base = ((size_t)(kc * BATCH + b) * NROW + r) * HIDDEN + col;
            *(float2*)(g_ctxp + base) = make_float2(acc[m][n][0], acc[m][n][1]);
            *(float2*)(g_ctxp + base + (size_t)8 * HIDDEN) =
                make_float2(acc[m][n][2], acc[m][n][3]);
        }
}

// ---------------- K6: o = sum_kc(ctxp) @ Wv_h^T per head -------------------
__global__ void __launch_bounds__(256) k_out1(const float* __restrict__ wkv) {
    int h = blockIdx.x, b = blockIdx.y;
    __shared__ float sC[4][64];
    __shared__ float sW[64][65];
    int tid = threadIdx.x;
    int xx = tid >> 6, d = tid & 63;
    float acc = 0.f;
    for (int j0 = 0; j0 < HIDDEN; j0 += 64) {
        __syncthreads();
        {
            float v = 0.f;
#pragma unroll
            for (int kc = 0; kc < KCH_CTX; kc++)
                v += g_ctxp[((size_t)(kc * BATCH + b) * NROW + h * 4 + xx) * HIDDEN + j0 + d];
            sC[xx][d] = v;
        }
        for (int i = tid; i < 64 * 64; i += 256) {
            int r = i >> 6, c = i & 63;
            sW[r][c] = wkv[(size_t)(HIDDEN + h * 64 + r) * HIDDEN + j0 + c];
        }
        __syncthreads();
#pragma unroll
        for (int jj = 0; jj < 64; jj++) acc += sC[xx][jj] * sW[d][jj];
    }
    g_o[(size_t)(b * 4 + xx) * HIDDEN + h * 64 + d] = acc;
}

// ---------------- K7: out = o @ w_out^T + b_out ----------------------------
__global__ void __launch_bounds__(256) k_out2(const float* __restrict__ wout,
                                              const float* __restrict__ bout,
                                              float* __restrict__ out) {
    int e0 = blockIdx.x * 256, b = blockIdx.y;
    __shared__ float sO[4][HIDDEN];
    __shared__ float sW[256][33];
    int tid = threadIdx.x;
    for (int i = tid; i < 4 * HIDDEN; i += 256) {
        int r = i / HIDDEN, c = i % HIDDEN;
        sO[r][c] = g_o[(size_t)(b * 4 + r) * HIDDEN + c];
    }
    float a0 = 0.f, a1 = 0.f, a2 = 0.f, a3 = 0.f;
    for (int kc = 0; kc < 24; kc++) {
        int k0 = kc * 32;
        __syncthreads();
        for (int i = tid; i < 256 * 32; i += 256) {
            int r = i >> 5, c = i & 31;
            sW[r][c] = wout[(size_t)(e0 + r) * HIDDEN + k0 + c];
        }
        __syncthreads();
#pragma unroll
        for (int kk = 0; kk < 32; kk++) {
            float w = sW[tid][kk];
            a0 += sO[0][k0 + kk] * w;
            a1 += sO[1][k0 + kk] * w;
            a2 += sO[2][k0 + kk] * w;
            a3 += sO[3][k0 + kk] * w;
        }
    }
    float bb = bout[e0 + tid];
    out[(size_t)(b * 4 + 0) * HIDDEN + e0 + tid] = a0 + bb;
    out[(size_t)(b * 4 + 1) * HIDDEN + e0 + tid] = a1 + bb;
    out[(size_t)(b * 4 + 2) * HIDDEN + e0 + tid] = a2 + bb;
    out[(size_t)(b * 4 + 3) * HIDDEN + e0 + tid] = a3 + bb;
}

// ---------------- entry -----------------------------------------------------
extern "C" void kernel_launch(void* const* d_in, const int* in_sizes, int n_in,
                              void* d_out, int out_size) {
    const float* x     = (const float*)d_in[0];
    const float* w_kv  = (const float*)d_in[1];
    const float* w_q   = (const float*)d_in[2];
    const float* w_out = (const float*)d_in[3];
    const float* b_out = (const float*)d_in[4];
    float* out = (float*)d_out;

    const int smem_logits = (2 * LQ_SZ + 2 * LX_SZ) * 4;   // 81408 B
    const int smem_ctx    = (2 * CA_SZ + 2 * CX_SZ) * 4;   // 74240 B
    cudaFuncSetAttribute(k_logits, cudaFuncAttributeMaxDynamicSharedMemorySize, smem_logits);
    cudaFuncSetAttribute(k_ctx, cudaFuncAttributeMaxDynamicSharedMemorySize, smem_ctx);

    k_qproj<<<dim3(6, 8), 256>>>(x, w_q);
    k_qk<<<dim3(12, 8), 256>>>(w_kv);
    k_logits<<<dim3(32, 8), 256, smem_logits>>>(x);
    k_rowstats<<<BATCH * NROW, 256>>>();
    k_ctx<<<dim3(3, KCH_CTX, 8), 256, smem_ctx>>>(x);
    k_out1<<<dim3(12, 8), 256>>>(w_kv);
    k_out2<<<dim3(3, 8), 256>>>(w_out, b_out, out);
}